// round 8
// baseline (speedup 1.0000x reference)
#include <cuda_runtime.h>
#include <math.h>

// ---------------------------------------------------------------------------
// Problem constants
// ---------------------------------------------------------------------------
#define BB   16
#define CIN  32
#define COUT 64
#define NNODE 1024
#define TT   24
#define NT   (NNODE*TT)        // 24576
#define SDIM 16
#define EB   (SDIM*BB*TT)      // 6144  cols of Ubig / Z
#define JCOLS (BB*COUT*TT)     // 24576 cols of XSp / Y1p / Y2r
#define BIG  (BB*COUT*NT)      // 25165824

// ---------------------------------------------------------------------------
// Scratch (static device globals -- no allocation allowed)
// ---------------------------------------------------------------------------
__device__ __align__(16) float g_delay[NT];
__device__ __align__(16) float g_M[NNODE*COUT];
__device__ __align__(16) float g_rowsum[NNODE];
__device__ __align__(16) float g_u[BB*NT];
__device__ __align__(16) float g_Ubig[NNODE*EB];
__device__ __align__(16) float g_Z[NNODE*EB];
__device__ __align__(16) float g_D[BIG];
__device__ __align__(16) float g_Qt[BIG];
__device__ __align__(16) float g_xin1[BIG];
__device__ __align__(16) float g_x1[BIG];
__device__ __align__(16) float g_XSp[(size_t)NNODE*JCOLS];
__device__ __align__(16) float g_Y1p[(size_t)NNODE*JCOLS];
__device__ __align__(16) float g_Y2r[(size_t)NNODE*JCOLS];

__device__ __forceinline__ float sigmoidf_(float z) {
    return 1.f / (1.f + __expf(-z));
}

// ---------------------------------------------------------------------------
// Precompute: delay(n,t) = sigmoid(tanh(CD@Wd)), M(n,o) = sum_e CS[n,e]*W_mii[o,e]
// ---------------------------------------------------------------------------
__global__ void precompute_kernel(const float* __restrict__ CD,
                                  const float* __restrict__ Wd,
                                  const float* __restrict__ CS,
                                  const float* __restrict__ W_mii) {
    int idx = blockIdx.x * 256 + threadIdx.x;
    if (idx < NT) {
        int n = idx / TT, t = idx - n * TT;
        float a = 0.f;
#pragma unroll
        for (int d = 0; d < 16; d++) a = fmaf(CD[n * 16 + d], Wd[d * TT + t], a);
        g_delay[idx] = sigmoidf_(tanhf(a));
    }
    if (idx < NNODE * COUT) {
        int n = idx / COUT, o = idx - n * COUT;
        float a = 0.f;
#pragma unroll
        for (int e = 0; e < 16; e++) a = fmaf(CS[n * 16 + e], W_mii[o * 16 + e], a);
        g_M[idx] = a;
    }
}

__global__ void rowsum_kernel(const float* __restrict__ adj) {
    __shared__ float red[256];
    int n = blockIdx.x;
    float s = 0.f;
    for (int m = threadIdx.x; m < NNODE; m += 256) s += adj[(size_t)n * NNODE + m];
    red[threadIdx.x] = s;
    __syncthreads();
    for (int w = 128; w > 0; w >>= 1) {
        if (threadIdx.x < w) red[threadIdx.x] += red[threadIdx.x + w];
        __syncthreads();
    }
    if (threadIdx.x == 0) g_rowsum[n] = red[0];
}

// ---------------------------------------------------------------------------
// K1: x -> D (with delay), Qt, x_input1, u, Ubig
//   block: (j-tile of 64, b). 256 threads. thread = (o, j-quarter of 16)
// ---------------------------------------------------------------------------
__global__ void k1_kernel(const float* __restrict__ x, const float* __restrict__ CS,
                          const float* __restrict__ W_de, const float* __restrict__ b_de,
                          const float* __restrict__ W_pro, const float* __restrict__ b_pro,
                          const float* __restrict__ W_1, const float* __restrict__ b_1,
                          const float* __restrict__ Wq, const float* __restrict__ bq) {
    __shared__ float xs[32][64];
    int b = blockIdx.y;
    int j0 = blockIdx.x * 64;
    int tid = threadIdx.x;

    for (int p = tid; p < 2048; p += 256) {
        int i = p >> 6, jj = p & 63;
        xs[i][jj] = x[(size_t)b * 32 * NT + (size_t)i * NT + j0 + jj];
    }
    __syncthreads();

    // u + Ubig (rank-16 factorization input)
    if (tid < 64) {
        int j = j0 + tid;
        float u = __ldg(&b_pro[0]);
#pragma unroll
        for (int i = 0; i < 32; i++) u = fmaf(__ldg(&W_pro[i]), xs[i][tid], u);
        g_u[(size_t)b * NT + j] = u;
        int n = j / TT, t = j - n * TT;
#pragma unroll
        for (int e = 0; e < 16; e++)
            g_Ubig[(size_t)n * EB + e * (BB * TT) + b * TT + t] = __ldg(&CS[n * 16 + e]) * u;
    }

    // D / Qt / x_input1 : three 64x32 conv1x1s
    int o = tid >> 2, jq = tid & 3;
    int jb = jq * 16;
    float aD[16], aQ[16], aW[16];
    float bd = __ldg(&b_de[o]), bqq = __ldg(&bq[o]), bw = __ldg(&b_1[o]);
#pragma unroll
    for (int m = 0; m < 16; m++) { aD[m] = bd; aQ[m] = bqq; aW[m] = bw; }
    for (int i = 0; i < 32; i++) {
        float wd = __ldg(&W_de[o * 32 + i]);
        float wq = __ldg(&Wq[o * 32 + i]);
        float w1 = __ldg(&W_1[o * 32 + i]);
#pragma unroll
        for (int m = 0; m < 16; m++) {
            float xv = xs[i][jb + m];
            aD[m] = fmaf(wd, xv, aD[m]);
            aQ[m] = fmaf(wq, xv, aQ[m]);
            aW[m] = fmaf(w1, xv, aW[m]);
        }
    }
    size_t base = (size_t)b * COUT * NT + (size_t)o * NT + j0 + jb;
#pragma unroll
    for (int m = 0; m < 16; m++) {
        float dly = g_delay[j0 + jb + m];
        g_D[base + m] = aD[m] * dly;
        g_Qt[base + m] = aQ[m];
        g_xin1[base + m] = aW[m];
    }
}

// ---------------------------------------------------------------------------
// Generic fp32 GEMM: C = alpha * A(1024 x 1024) @ B(1024 x Nc), row-major.
// 128x128x8 tile, 256 threads, 8x8 per thread.
// ---------------------------------------------------------------------------
__global__ void sgemm128(const float* __restrict__ A, const float* __restrict__ B,
                         float* __restrict__ C, int Nc, float alpha) {
    const int Kd = 1024;
    __shared__ float As[8][128];
    __shared__ float Bs[8][128];
    int tid = threadIdx.x;
    int bm = blockIdx.y * 128;
    int bn = blockIdx.x * 128;
    int tx = tid & 15, ty = tid >> 4;

    float acc[8][8];
#pragma unroll
    for (int i = 0; i < 8; i++)
#pragma unroll
        for (int j = 0; j < 8; j++) acc[i][j] = 0.f;

    int a_row = tid >> 1;
    int a_col = (tid & 1) << 2;
    int b_row = tid >> 5;
    int b_col = (tid & 31) << 2;
    const float* Aptr = A + (size_t)(bm + a_row) * Kd + a_col;
    const float* Bptr = B + (size_t)b_row * Nc + bn + b_col;

    for (int k0 = 0; k0 < Kd; k0 += 8) {
        float4 av = *(const float4*)(Aptr + k0);
        As[a_col + 0][a_row] = av.x;
        As[a_col + 1][a_row] = av.y;
        As[a_col + 2][a_row] = av.z;
        As[a_col + 3][a_row] = av.w;
        float4 bv = *(const float4*)(Bptr + (size_t)k0 * Nc);
        *(float4*)&Bs[b_row][b_col] = bv;
        __syncthreads();
#pragma unroll
        for (int kk = 0; kk < 8; kk++) {
            float a[8], bb[8];
            *(float4*)&a[0] = *(const float4*)&As[kk][ty * 4];
            *(float4*)&a[4] = *(const float4*)&As[kk][64 + ty * 4];
            *(float4*)&bb[0] = *(const float4*)&Bs[kk][tx * 4];
            *(float4*)&bb[4] = *(const float4*)&Bs[kk][64 + tx * 4];
#pragma unroll
            for (int i = 0; i < 8; i++)
#pragma unroll
                for (int j = 0; j < 8; j++) acc[i][j] = fmaf(a[i], bb[j], acc[i][j]);
        }
        __syncthreads();
    }

#pragma unroll
    for (int ih = 0; ih < 2; ih++)
#pragma unroll
        for (int i = 0; i < 4; i++) {
            int r = bm + ih * 64 + ty * 4 + i;
#pragma unroll
            for (int jh = 0; jh < 2; jh++) {
                float4 v;
                v.x = alpha * acc[ih * 4 + i][jh * 4 + 0];
                v.y = alpha * acc[ih * 4 + i][jh * 4 + 1];
                v.z = alpha * acc[ih * 4 + i][jh * 4 + 2];
                v.w = alpha * acc[ih * 4 + i][jh * 4 + 3];
                *(float4*)&C[(size_t)r * Nc + bn + jh * 64 + tx * 4] = v;
            }
        }
}

// ---------------------------------------------------------------------------
// Attn1 (temporal): per (b,n) block. K,V from D; Q precomputed; + x_input1;
// then conv_t (kernel 3, pad 1) -> x1
// ---------------------------------------------------------------------------
__global__ void attn1_kernel(const float* __restrict__ Wk, const float* __restrict__ bk,
                             const float* __restrict__ Wv, const float* __restrict__ bv,
                             const float* __restrict__ Wc1, const float* __restrict__ bc1) {
    __shared__ float sD[64][24];
    __shared__ float sQ[64][24];
    __shared__ float sK[64][24];
    __shared__ float sV[64][24];
    __shared__ float sA[24][25];
    int b = blockIdx.y, n = blockIdx.x, tid = threadIdx.x;
    size_t base = (((size_t)b * 64) * NNODE + n) * TT;

    for (int p = tid; p < 1536; p += 256) {
        int c = p / 24, t = p - c * 24;
        size_t g = base + (size_t)c * NT + t;
        sD[c][t] = g_D[g];
        sQ[c][t] = g_Qt[g];
    }
    __syncthreads();

    { // K, V
        int c = tid >> 2, sq = tid & 3;
        float ak[6], av[6];
        float bkc = __ldg(&bk[c]), bvc = __ldg(&bv[c]);
#pragma unroll
        for (int m = 0; m < 6; m++) { ak[m] = bkc; av[m] = bvc; }
        for (int i = 0; i < 64; i++) {
            float wk = __ldg(&Wk[c * 64 + i]);
            float wv = __ldg(&Wv[c * 64 + i]);
#pragma unroll
            for (int m = 0; m < 6; m++) {
                float d = sD[i][sq + 4 * m];
                ak[m] = fmaf(wk, d, ak[m]);
                av[m] = fmaf(wv, d, av[m]);
            }
        }
#pragma unroll
        for (int m = 0; m < 6; m++) { sK[c][sq + 4 * m] = ak[m]; sV[c][sq + 4 * m] = av[m]; }
    }
    __syncthreads();

    for (int p = tid; p < 576; p += 256) { // scores
        int t = p / 24, s = p - t * 24;
        float acc = 0.f;
#pragma unroll
        for (int c = 0; c < 64; c++) acc = fmaf(sQ[c][t], sK[c][s], acc);
        sA[t][s] = acc * 0.125f;
    }
    __syncthreads();

    if (tid < 24) { // softmax over s
        float mx = -1e30f;
        for (int s = 0; s < 24; s++) mx = fmaxf(mx, sA[tid][s]);
        float sum = 0.f;
        for (int s = 0; s < 24; s++) { float e = __expf(sA[tid][s] - mx); sA[tid][s] = e; sum += e; }
        float inv = 1.f / sum;
        for (int s = 0; s < 24; s++) sA[tid][s] *= inv;
    }
    __syncthreads();

    for (int p = tid; p < 1536; p += 256) { // XD = A@V + x_input1 (into sD)
        int c = p / 24, t = p - c * 24;
        float acc = 0.f;
#pragma unroll
        for (int s = 0; s < 24; s++) acc = fmaf(sA[t][s], sV[c][s], acc);
        size_t g = base + (size_t)c * NT + t;
        sD[c][t] = acc + g_xin1[g];
    }
    __syncthreads();

    { // temporal conv (k=3, pad 1) -> x1
        int o = tid >> 2, tq = tid & 3;
        float acc[6];
        float bo = __ldg(&bc1[o]);
#pragma unroll
        for (int m = 0; m < 6; m++) acc[m] = bo;
        for (int i = 0; i < 64; i++) {
            float w0 = __ldg(&Wc1[(o * 64 + i) * 3 + 0]);
            float w1 = __ldg(&Wc1[(o * 64 + i) * 3 + 1]);
            float w2 = __ldg(&Wc1[(o * 64 + i) * 3 + 2]);
#pragma unroll
            for (int m = 0; m < 6; m++) {
                int t = tq + 4 * m;
                float xm = (t > 0) ? sD[i][t - 1] : 0.f;
                float x0 = sD[i][t];
                float xp = (t < 23) ? sD[i][t + 1] : 0.f;
                acc[m] = fmaf(w0, xm, fmaf(w1, x0, fmaf(w2, xp, acc[m])));
            }
        }
#pragma unroll
        for (int m = 0; m < 6; m++) {
            int t = tq + 4 * m;
            g_x1[base + (size_t)o * NT + t] = acc[m];
        }
    }
}

// ---------------------------------------------------------------------------
// Attn2 (spatial): per (b,n). S reconstructed from rank-16 Z; Q from x1;
// writes XS directly in packed (n, b*c*t) layout for the cheby GEMMs.
// ---------------------------------------------------------------------------
__global__ void attn2_kernel(const float* __restrict__ W_mii, const float* __restrict__ b_mii,
                             const float* __restrict__ Wq, const float* __restrict__ bq,
                             const float* __restrict__ Wk, const float* __restrict__ bk,
                             const float* __restrict__ Wv, const float* __restrict__ bv) {
    __shared__ float sS[64][24];
    __shared__ float sQ[64][24];
    __shared__ float sK[64][24];
    __shared__ float sV[64][24];
    __shared__ float sA[24][25];
    __shared__ float sZ[16][24];
    __shared__ float su[24];
    int b = blockIdx.y, n = blockIdx.x, tid = threadIdx.x;
    size_t base = (((size_t)b * 64) * NNODE + n) * TT;

    for (int p = tid; p < 1536; p += 256) { // x1 tile staged in sV
        int c = p / 24, t = p - c * 24;
        sV[c][t] = g_x1[base + (size_t)c * NT + t];
    }
    for (int p = tid; p < 384; p += 256) {
        int e = p / 24, t = p - e * 24;
        sZ[e][t] = g_Z[(size_t)n * EB + e * (BB * TT) + b * TT + t];
    }
    if (tid < 24) su[tid] = g_u[(size_t)b * NT + n * TT + tid];
    __syncthreads();

    { // Q from x1
        int c = tid >> 2, tq = tid & 3;
        float a[6];
        float bqc = __ldg(&bq[c]);
#pragma unroll
        for (int m = 0; m < 6; m++) a[m] = bqc;
        for (int i = 0; i < 64; i++) {
            float w = __ldg(&Wq[c * 64 + i]);
#pragma unroll
            for (int m = 0; m < 6; m++) a[m] = fmaf(w, sV[i][tq + 4 * m], a[m]);
        }
#pragma unroll
        for (int m = 0; m < 6; m++) sQ[c][tq + 4 * m] = a[m];
    }
    { // S = b_mii*(1+rowsum) + u*M + W_mii@Z
        float rs1 = 1.f + g_rowsum[n];
        for (int p = tid; p < 1536; p += 256) {
            int c = p / 24, t = p - c * 24;
            float a = __ldg(&b_mii[c]) * rs1 + su[t] * g_M[n * 64 + c];
#pragma unroll
            for (int e = 0; e < 16; e++) a = fmaf(__ldg(&W_mii[c * 16 + e]), sZ[e][t], a);
            sS[c][t] = a;
        }
    }
    __syncthreads();

    { // K, V from S (overwrite sK/sV)
        int c = tid >> 2, sq = tid & 3;
        float ak[6], av[6];
        float bkc = __ldg(&bk[c]), bvc = __ldg(&bv[c]);
#pragma unroll
        for (int m = 0; m < 6; m++) { ak[m] = bkc; av[m] = bvc; }
        for (int i = 0; i < 64; i++) {
            float wk = __ldg(&Wk[c * 64 + i]);
            float wv = __ldg(&Wv[c * 64 + i]);
#pragma unroll
            for (int m = 0; m < 6; m++) {
                float d = sS[i][sq + 4 * m];
                ak[m] = fmaf(wk, d, ak[m]);
                av[m] = fmaf(wv, d, av[m]);
            }
        }
#pragma unroll
        for (int m = 0; m < 6; m++) { sK[c][sq + 4 * m] = ak[m]; sV[c][sq + 4 * m] = av[m]; }
    }
    __syncthreads();

    for (int p = tid; p < 576; p += 256) {
        int t = p / 24, s = p - t * 24;
        float acc = 0.f;
#pragma unroll
        for (int c = 0; c < 64; c++) acc = fmaf(sQ[c][t], sK[c][s], acc);
        sA[t][s] = acc * 0.125f;
    }
    __syncthreads();
    if (tid < 24) {
        float mx = -1e30f;
        for (int s = 0; s < 24; s++) mx = fmaxf(mx, sA[tid][s]);
        float sum = 0.f;
        for (int s = 0; s < 24; s++) { float e = __expf(sA[tid][s] - mx); sA[tid][s] = e; sum += e; }
        float inv = 1.f / sum;
        for (int s = 0; s < 24; s++) sA[tid][s] *= inv;
    }
    __syncthreads();

    for (int p = tid; p < 1536; p += 256) { // XS -> packed layout
        int c = p / 24, t = p - c * 24;
        float acc = 0.f;
#pragma unroll
        for (int s = 0; s < 24; s++) acc = fmaf(sA[t][s], sV[c][s], acc);
        g_XSp[(size_t)n * JCOLS + (b * 64 + c) * 24 + t] = acc;
    }
}

// ---------------------------------------------------------------------------
// Combine: y2 = Y2r - XS; x2 = W_g @ [XS;Y1;y2] + b_g; out = (filt + xin1)*sig(gate)
// ---------------------------------------------------------------------------
__global__ void combine_kernel(const float* __restrict__ Wg, const float* __restrict__ bg,
                               float* __restrict__ out) {
    __shared__ float xs[64][24];
    __shared__ float y1[64][24];
    __shared__ float y2[64][24];
    int b = blockIdx.y, n = blockIdx.x, tid = threadIdx.x;
    size_t row = (size_t)n * JCOLS;
    int cb = b * 64 * 24;

    for (int p = tid; p < 1536; p += 256) {
        int c = p / 24, t = p - c * 24;
        size_t g = row + cb + c * 24 + t;
        float a = g_XSp[g];
        xs[c][t] = a;
        y1[c][t] = g_Y1p[g];
        y2[c][t] = g_Y2r[g] - a;   // (2*S^2 - I) @ XS
    }
    __syncthreads();

    int o = tid & 63, q = tid >> 6;
    float f[6], gg[6];
    float bf = __ldg(&bg[o]), bgt = __ldg(&bg[o + 64]);
#pragma unroll
    for (int m = 0; m < 6; m++) { f[m] = bf; gg[m] = bgt; }
    for (int c = 0; c < 64; c++) {
        float w0f = __ldg(&Wg[o * 192 + 3 * c + 0]);
        float w1f = __ldg(&Wg[o * 192 + 3 * c + 1]);
        float w2f = __ldg(&Wg[o * 192 + 3 * c + 2]);
        float w0g = __ldg(&Wg[(o + 64) * 192 + 3 * c + 0]);
        float w1g = __ldg(&Wg[(o + 64) * 192 + 3 * c + 1]);
        float w2g = __ldg(&Wg[(o + 64) * 192 + 3 * c + 2]);
#pragma unroll
        for (int m = 0; m < 6; m++) {
            int t = q + 4 * m;
            float a = xs[c][t], b1 = y1[c][t], b2 = y2[c][t];
            f[m] = fmaf(w0f, a, fmaf(w1f, b1, fmaf(w2f, b2, f[m])));
            gg[m] = fmaf(w0g, a, fmaf(w1g, b1, fmaf(w2g, b2, gg[m])));
        }
    }
    size_t obase = (((size_t)b * 64 + o) * NNODE + n) * TT;
#pragma unroll
    for (int m = 0; m < 6; m++) {
        int t = q + 4 * m;
        out[obase + t] = (f[m] + g_xin1[obase + t]) * sigmoidf_(gg[m]);
    }
}

// ---------------------------------------------------------------------------
// Host launcher
// ---------------------------------------------------------------------------
extern "C" void kernel_launch(void* const* d_in, const int* in_sizes, int n_in,
                              void* d_out, int out_size) {
    const float* x        = (const float*)d_in[0];
    const float* supports = (const float*)d_in[1];
    const float* CD       = (const float*)d_in[2];
    const float* CS       = (const float*)d_in[3];
    const float* adj      = (const float*)d_in[4];
    const float* W_de     = (const float*)d_in[5];
    const float* b_de     = (const float*)d_in[6];
    const float* Wd       = (const float*)d_in[7];
    const float* W_pro    = (const float*)d_in[8];
    const float* b_pro    = (const float*)d_in[9];
    const float* W_mii    = (const float*)d_in[10];
    const float* b_mii    = (const float*)d_in[11];
    const float* W_1      = (const float*)d_in[12];
    const float* b_1      = (const float*)d_in[13];
    const float* Wq_t     = (const float*)d_in[14];
    const float* bq_t     = (const float*)d_in[15];
    const float* Wk_t     = (const float*)d_in[16];
    const float* bk_t     = (const float*)d_in[17];
    const float* Wv_t     = (const float*)d_in[18];
    const float* bv_t     = (const float*)d_in[19];
    const float* W_c1     = (const float*)d_in[20];
    const float* b_c1     = (const float*)d_in[21];
    const float* Wq_s     = (const float*)d_in[22];
    const float* bq_s     = (const float*)d_in[23];
    const float* Wk_s     = (const float*)d_in[24];
    const float* bk_s     = (const float*)d_in[25];
    const float* Wv_s     = (const float*)d_in[26];
    const float* bv_s     = (const float*)d_in[27];
    const float* W_g      = (const float*)d_in[28];
    const float* b_g      = (const float*)d_in[29];
    float* out = (float*)d_out;

    float *p_Ubig, *p_Z, *p_XSp, *p_Y1p, *p_Y2r;
    cudaGetSymbolAddress((void**)&p_Ubig, g_Ubig);
    cudaGetSymbolAddress((void**)&p_Z,    g_Z);
    cudaGetSymbolAddress((void**)&p_XSp,  g_XSp);
    cudaGetSymbolAddress((void**)&p_Y1p,  g_Y1p);
    cudaGetSymbolAddress((void**)&p_Y2r,  g_Y2r);

    // small precompute
    precompute_kernel<<<256, 256>>>(CD, Wd, CS, W_mii);
    rowsum_kernel<<<NNODE, 256>>>(adj);

    // stage 1: conv1x1 fan-out from x
    k1_kernel<<<dim3(NT / 64, BB), 256>>>(x, CS, W_de, b_de, W_pro, b_pro,
                                          W_1, b_1, Wq_t, bq_t);

    // rank-16 graph propagation: Z = adj @ Ubig
    sgemm128<<<dim3(EB / 128, 8), 256>>>(adj, p_Ubig, p_Z, EB, 1.f);

    // temporal attention + temporal conv -> x1
    attn1_kernel<<<dim3(NNODE, BB), 256>>>(Wk_t, bk_t, Wv_t, bv_t, W_c1, b_c1);

    // spatial attention (S reconstructed from Z) -> XS packed
    attn2_kernel<<<dim3(NNODE, BB), 256>>>(W_mii, b_mii, Wq_s, bq_s, Wk_s, bk_s, Wv_s, bv_s);

    // cheby via recurrence: Y1 = S@XS ; Y2r = 2*S@Y1 (the -XS is folded into combine)
    sgemm128<<<dim3(JCOLS / 128, 8), 256>>>(supports, p_XSp, p_Y1p, JCOLS, 1.f);
    sgemm128<<<dim3(JCOLS / 128, 8), 256>>>(supports, p_Y1p, p_Y2r, JCOLS, 2.f);

    // W_g epilogue + residual + gate
    combine_kernel<<<dim3(NNODE, BB), 256>>>(W_g, b_g, out);

    (void)in_sizes; (void)n_in; (void)out_size;
}

// round 9
// speedup vs baseline: 1.0011x; 1.0011x over previous
#include <cuda_runtime.h>
#include <math.h>

// ---------------------------------------------------------------------------
// Problem constants
// ---------------------------------------------------------------------------
#define BB   16
#define CIN  32
#define COUT 64
#define NNODE 1024
#define TT   24
#define NT   (NNODE*TT)        // 24576
#define SDIM 16
#define EB   (SDIM*BB*TT)      // 6144  cols of Ubig / Z
#define JCOLS (BB*COUT*TT)     // 24576 cols of XSp / Y1p / Y2r
#define BIG  (BB*COUT*NT)      // 25165824

// ---------------------------------------------------------------------------
// Scratch (static device globals -- no allocation allowed)
// ---------------------------------------------------------------------------
__device__ __align__(16) float g_delay[NT];
__device__ __align__(16) float g_M[NNODE*COUT];
__device__ __align__(16) float g_rowsum[NNODE];
__device__ __align__(16) float g_u[BB*NT];
__device__ __align__(16) float g_Ubig[NNODE*EB];
__device__ __align__(16) float g_Z[NNODE*EB];
__device__ __align__(16) float g_D[BIG];
__device__ __align__(16) float g_Qt[BIG];
__device__ __align__(16) float g_xin1[BIG];
__device__ __align__(16) float g_x1[BIG];
__device__ __align__(16) float g_XSp[(size_t)NNODE*JCOLS];
__device__ __align__(16) float g_Y1p[(size_t)NNODE*JCOLS];
__device__ __align__(16) float g_Y2r[(size_t)NNODE*JCOLS];

__device__ __forceinline__ float sigmoidf_(float z) {
    return 1.f / (1.f + __expf(-z));
}

// ---------------------------------------------------------------------------
// Precompute: delay(n,t) = sigmoid(tanh(CD@Wd)), M(n,o) = sum_e CS[n,e]*W_mii[o,e]
// ---------------------------------------------------------------------------
__global__ void precompute_kernel(const float* __restrict__ CD,
                                  const float* __restrict__ Wd,
                                  const float* __restrict__ CS,
                                  const float* __restrict__ W_mii) {
    int idx = blockIdx.x * 256 + threadIdx.x;
    if (idx < NT) {
        int n = idx / TT, t = idx - n * TT;
        float a = 0.f;
#pragma unroll
        for (int d = 0; d < 16; d++) a = fmaf(CD[n * 16 + d], Wd[d * TT + t], a);
        g_delay[idx] = sigmoidf_(tanhf(a));
    }
    if (idx < NNODE * COUT) {
        int n = idx / COUT, o = idx - n * COUT;
        float a = 0.f;
#pragma unroll
        for (int e = 0; e < 16; e++) a = fmaf(CS[n * 16 + e], W_mii[o * 16 + e], a);
        g_M[idx] = a;
    }
}

__global__ void rowsum_kernel(const float* __restrict__ adj) {
    __shared__ float red[256];
    int n = blockIdx.x;
    float s = 0.f;
    for (int m = threadIdx.x; m < NNODE; m += 256) s += adj[(size_t)n * NNODE + m];
    red[threadIdx.x] = s;
    __syncthreads();
    for (int w = 128; w > 0; w >>= 1) {
        if (threadIdx.x < w) red[threadIdx.x] += red[threadIdx.x + w];
        __syncthreads();
    }
    if (threadIdx.x == 0) g_rowsum[n] = red[0];
}

// ---------------------------------------------------------------------------
// K1: x -> D (with delay), Qt, x_input1, u, Ubig
//   block: (j-tile of 64, b). 256 threads. thread = (o, j-quarter of 16)
// ---------------------------------------------------------------------------
__global__ void k1_kernel(const float* __restrict__ x, const float* __restrict__ CS,
                          const float* __restrict__ W_de, const float* __restrict__ b_de,
                          const float* __restrict__ W_pro, const float* __restrict__ b_pro,
                          const float* __restrict__ W_1, const float* __restrict__ b_1,
                          const float* __restrict__ Wq, const float* __restrict__ bq) {
    __shared__ float xs[32][64];
    int b = blockIdx.y;
    int j0 = blockIdx.x * 64;
    int tid = threadIdx.x;

    for (int p = tid; p < 2048; p += 256) {
        int i = p >> 6, jj = p & 63;
        xs[i][jj] = x[(size_t)b * 32 * NT + (size_t)i * NT + j0 + jj];
    }
    __syncthreads();

    // u + Ubig (rank-16 factorization input)
    if (tid < 64) {
        int j = j0 + tid;
        float u = __ldg(&b_pro[0]);
#pragma unroll
        for (int i = 0; i < 32; i++) u = fmaf(__ldg(&W_pro[i]), xs[i][tid], u);
        g_u[(size_t)b * NT + j] = u;
        int n = j / TT, t = j - n * TT;
#pragma unroll
        for (int e = 0; e < 16; e++)
            g_Ubig[(size_t)n * EB + e * (BB * TT) + b * TT + t] = __ldg(&CS[n * 16 + e]) * u;
    }

    // D / Qt / x_input1 : three 64x32 conv1x1s
    int o = tid >> 2, jq = tid & 3;
    int jb = jq * 16;
    float aD[16], aQ[16], aW[16];
    float bd = __ldg(&b_de[o]), bqq = __ldg(&bq[o]), bw = __ldg(&b_1[o]);
#pragma unroll
    for (int m = 0; m < 16; m++) { aD[m] = bd; aQ[m] = bqq; aW[m] = bw; }
    for (int i = 0; i < 32; i++) {
        float wd = __ldg(&W_de[o * 32 + i]);
        float wq = __ldg(&Wq[o * 32 + i]);
        float w1 = __ldg(&W_1[o * 32 + i]);
#pragma unroll
        for (int m = 0; m < 16; m++) {
            float xv = xs[i][jb + m];
            aD[m] = fmaf(wd, xv, aD[m]);
            aQ[m] = fmaf(wq, xv, aQ[m]);
            aW[m] = fmaf(w1, xv, aW[m]);
        }
    }
    size_t base = (size_t)b * COUT * NT + (size_t)o * NT + j0 + jb;
#pragma unroll
    for (int m = 0; m < 16; m++) {
        float dly = g_delay[j0 + jb + m];
        g_D[base + m] = aD[m] * dly;
        g_Qt[base + m] = aQ[m];
        g_xin1[base + m] = aW[m];
    }
}

// ---------------------------------------------------------------------------
// Generic fp32 GEMM: C = alpha * A(1024 x 1024) @ B(1024 x Nc), row-major.
// 128x128x8 tile, 256 threads, 8x8 per thread.
// ---------------------------------------------------------------------------
__global__ void sgemm128(const float* __restrict__ A, const float* __restrict__ B,
                         float* __restrict__ C, int Nc, float alpha) {
    const int Kd = 1024;
    __shared__ float As[8][128];
    __shared__ float Bs[8][128];
    int tid = threadIdx.x;
    int bm = blockIdx.y * 128;
    int bn = blockIdx.x * 128;
    int tx = tid & 15, ty = tid >> 4;

    float acc[8][8];
#pragma unroll
    for (int i = 0; i < 8; i++)
#pragma unroll
        for (int j = 0; j < 8; j++) acc[i][j] = 0.f;

    int a_row = tid >> 1;
    int a_col = (tid & 1) << 2;
    int b_row = tid >> 5;
    int b_col = (tid & 31) << 2;
    const float* Aptr = A + (size_t)(bm + a_row) * Kd + a_col;
    const float* Bptr = B + (size_t)b_row * Nc + bn + b_col;

    for (int k0 = 0; k0 < Kd; k0 += 8) {
        float4 av = *(const float4*)(Aptr + k0);
        As[a_col + 0][a_row] = av.x;
        As[a_col + 1][a_row] = av.y;
        As[a_col + 2][a_row] = av.z;
        As[a_col + 3][a_row] = av.w;
        float4 bv = *(const float4*)(Bptr + (size_t)k0 * Nc);
        *(float4*)&Bs[b_row][b_col] = bv;
        __syncthreads();
#pragma unroll
        for (int kk = 0; kk < 8; kk++) {
            float a[8], bb[8];
            *(float4*)&a[0] = *(const float4*)&As[kk][ty * 4];
            *(float4*)&a[4] = *(const float4*)&As[kk][64 + ty * 4];
            *(float4*)&bb[0] = *(const float4*)&Bs[kk][tx * 4];
            *(float4*)&bb[4] = *(const float4*)&Bs[kk][64 + tx * 4];
#pragma unroll
            for (int i = 0; i < 8; i++)
#pragma unroll
                for (int j = 0; j < 8; j++) acc[i][j] = fmaf(a[i], bb[j], acc[i][j]);
        }
        __syncthreads();
    }

#pragma unroll
    for (int ih = 0; ih < 2; ih++)
#pragma unroll
        for (int i = 0; i < 4; i++) {
            int r = bm + ih * 64 + ty * 4 + i;
#pragma unroll
            for (int jh = 0; jh < 2; jh++) {
                float4 v;
                v.x = alpha * acc[ih * 4 + i][jh * 4 + 0];
                v.y = alpha * acc[ih * 4 + i][jh * 4 + 1];
                v.z = alpha * acc[ih * 4 + i][jh * 4 + 2];
                v.w = alpha * acc[ih * 4 + i][jh * 4 + 3];
                *(float4*)&C[(size_t)r * Nc + bn + jh * 64 + tx * 4] = v;
            }
        }
}

// ---------------------------------------------------------------------------
// Attn1 (temporal): per (b,n) block. K,V from D; Q precomputed; + x_input1;
// then conv_t (kernel 3, pad 1) -> x1
// ---------------------------------------------------------------------------
__global__ void attn1_kernel(const float* __restrict__ Wk, const float* __restrict__ bk,
                             const float* __restrict__ Wv, const float* __restrict__ bv,
                             const float* __restrict__ Wc1, const float* __restrict__ bc1) {
    __shared__ float sD[64][24];
    __shared__ float sQ[64][24];
    __shared__ float sK[64][24];
    __shared__ float sV[64][24];
    __shared__ float sA[24][25];
    int b = blockIdx.y, n = blockIdx.x, tid = threadIdx.x;
    size_t base = (((size_t)b * 64) * NNODE + n) * TT;

    for (int p = tid; p < 1536; p += 256) {
        int c = p / 24, t = p - c * 24;
        size_t g = base + (size_t)c * NT + t;
        sD[c][t] = g_D[g];
        sQ[c][t] = g_Qt[g];
    }
    __syncthreads();

    { // K, V
        int c = tid >> 2, sq = tid & 3;
        float ak[6], av[6];
        float bkc = __ldg(&bk[c]), bvc = __ldg(&bv[c]);
#pragma unroll
        for (int m = 0; m < 6; m++) { ak[m] = bkc; av[m] = bvc; }
        for (int i = 0; i < 64; i++) {
            float wk = __ldg(&Wk[c * 64 + i]);
            float wv = __ldg(&Wv[c * 64 + i]);
#pragma unroll
            for (int m = 0; m < 6; m++) {
                float d = sD[i][sq + 4 * m];
                ak[m] = fmaf(wk, d, ak[m]);
                av[m] = fmaf(wv, d, av[m]);
            }
        }
#pragma unroll
        for (int m = 0; m < 6; m++) { sK[c][sq + 4 * m] = ak[m]; sV[c][sq + 4 * m] = av[m]; }
    }
    __syncthreads();

    for (int p = tid; p < 576; p += 256) { // scores
        int t = p / 24, s = p - t * 24;
        float acc = 0.f;
#pragma unroll
        for (int c = 0; c < 64; c++) acc = fmaf(sQ[c][t], sK[c][s], acc);
        sA[t][s] = acc * 0.125f;
    }
    __syncthreads();

    if (tid < 24) { // softmax over s
        float mx = -1e30f;
        for (int s = 0; s < 24; s++) mx = fmaxf(mx, sA[tid][s]);
        float sum = 0.f;
        for (int s = 0; s < 24; s++) { float e = __expf(sA[tid][s] - mx); sA[tid][s] = e; sum += e; }
        float inv = 1.f / sum;
        for (int s = 0; s < 24; s++) sA[tid][s] *= inv;
    }
    __syncthreads();

    for (int p = tid; p < 1536; p += 256) { // XD = A@V + x_input1 (into sD)
        int c = p / 24, t = p - c * 24;
        float acc = 0.f;
#pragma unroll
        for (int s = 0; s < 24; s++) acc = fmaf(sA[t][s], sV[c][s], acc);
        size_t g = base + (size_t)c * NT + t;
        sD[c][t] = acc + g_xin1[g];
    }
    __syncthreads();

    { // temporal conv (k=3, pad 1) -> x1
        int o = tid >> 2, tq = tid & 3;
        float acc[6];
        float bo = __ldg(&bc1[o]);
#pragma unroll
        for (int m = 0; m < 6; m++) acc[m] = bo;
        for (int i = 0; i < 64; i++) {
            float w0 = __ldg(&Wc1[(o * 64 + i) * 3 + 0]);
            float w1 = __ldg(&Wc1[(o * 64 + i) * 3 + 1]);
            float w2 = __ldg(&Wc1[(o * 64 + i) * 3 + 2]);
#pragma unroll
            for (int m = 0; m < 6; m++) {
                int t = tq + 4 * m;
                float xm = (t > 0) ? sD[i][t - 1] : 0.f;
                float x0 = sD[i][t];
                float xp = (t < 23) ? sD[i][t + 1] : 0.f;
                acc[m] = fmaf(w0, xm, fmaf(w1, x0, fmaf(w2, xp, acc[m])));
            }
        }
#pragma unroll
        for (int m = 0; m < 6; m++) {
            int t = tq + 4 * m;
            g_x1[base + (size_t)o * NT + t] = acc[m];
        }
    }
}

// ---------------------------------------------------------------------------
// Attn2 (spatial): per (b,n). S reconstructed from rank-16 Z; Q from x1;
// writes XS directly in packed (n, b*c*t) layout for the cheby GEMMs.
// ---------------------------------------------------------------------------
__global__ void attn2_kernel(const float* __restrict__ W_mii, const float* __restrict__ b_mii,
                             const float* __restrict__ Wq, const float* __restrict__ bq,
                             const float* __restrict__ Wk, const float* __restrict__ bk,
                             const float* __restrict__ Wv, const float* __restrict__ bv) {
    __shared__ float sS[64][24];
    __shared__ float sQ[64][24];
    __shared__ float sK[64][24];
    __shared__ float sV[64][24];
    __shared__ float sA[24][25];
    __shared__ float sZ[16][24];
    __shared__ float su[24];
    int b = blockIdx.y, n = blockIdx.x, tid = threadIdx.x;
    size_t base = (((size_t)b * 64) * NNODE + n) * TT;

    for (int p = tid; p < 1536; p += 256) { // x1 tile staged in sV
        int c = p / 24, t = p - c * 24;
        sV[c][t] = g_x1[base + (size_t)c * NT + t];
    }
    for (int p = tid; p < 384; p += 256) {
        int e = p / 24, t = p - e * 24;
        sZ[e][t] = g_Z[(size_t)n * EB + e * (BB * TT) + b * TT + t];
    }
    if (tid < 24) su[tid] = g_u[(size_t)b * NT + n * TT + tid];
    __syncthreads();

    { // Q from x1
        int c = tid >> 2, tq = tid & 3;
        float a[6];
        float bqc = __ldg(&bq[c]);
#pragma unroll
        for (int m = 0; m < 6; m++) a[m] = bqc;
        for (int i = 0; i < 64; i++) {
            float w = __ldg(&Wq[c * 64 + i]);
#pragma unroll
            for (int m = 0; m < 6; m++) a[m] = fmaf(w, sV[i][tq + 4 * m], a[m]);
        }
#pragma unroll
        for (int m = 0; m < 6; m++) sQ[c][tq + 4 * m] = a[m];
    }
    { // S = b_mii*(1+rowsum) + u*M + W_mii@Z
        float rs1 = 1.f + g_rowsum[n];
        for (int p = tid; p < 1536; p += 256) {
            int c = p / 24, t = p - c * 24;
            float a = __ldg(&b_mii[c]) * rs1 + su[t] * g_M[n * 64 + c];
#pragma unroll
            for (int e = 0; e < 16; e++) a = fmaf(__ldg(&W_mii[c * 16 + e]), sZ[e][t], a);
            sS[c][t] = a;
        }
    }
    __syncthreads();

    { // K, V from S (overwrite sK/sV)
        int c = tid >> 2, sq = tid & 3;
        float ak[6], av[6];
        float bkc = __ldg(&bk[c]), bvc = __ldg(&bv[c]);
#pragma unroll
        for (int m = 0; m < 6; m++) { ak[m] = bkc; av[m] = bvc; }
        for (int i = 0; i < 64; i++) {
            float wk = __ldg(&Wk[c * 64 + i]);
            float wv = __ldg(&Wv[c * 64 + i]);
#pragma unroll
            for (int m = 0; m < 6; m++) {
                float d = sS[i][sq + 4 * m];
                ak[m] = fmaf(wk, d, ak[m]);
                av[m] = fmaf(wv, d, av[m]);
            }
        }
#pragma unroll
        for (int m = 0; m < 6; m++) { sK[c][sq + 4 * m] = ak[m]; sV[c][sq + 4 * m] = av[m]; }
    }
    __syncthreads();

    for (int p = tid; p < 576; p += 256) {
        int t = p / 24, s = p - t * 24;
        float acc = 0.f;
#pragma unroll
        for (int c = 0; c < 64; c++) acc = fmaf(sQ[c][t], sK[c][s], acc);
        sA[t][s] = acc * 0.125f;
    }
    __syncthreads();
    if (tid < 24) {
        float mx = -1e30f;
        for (int s = 0; s < 24; s++) mx = fmaxf(mx, sA[tid][s]);
        float sum = 0.f;
        for (int s = 0; s < 24; s++) { float e = __expf(sA[tid][s] - mx); sA[tid][s] = e; sum += e; }
        float inv = 1.f / sum;
        for (int s = 0; s < 24; s++) sA[tid][s] *= inv;
    }
    __syncthreads();

    for (int p = tid; p < 1536; p += 256) { // XS -> packed layout
        int c = p / 24, t = p - c * 24;
        float acc = 0.f;
#pragma unroll
        for (int s = 0; s < 24; s++) acc = fmaf(sA[t][s], sV[c][s], acc);
        g_XSp[(size_t)n * JCOLS + (b * 64 + c) * 24 + t] = acc;
    }
}

// ---------------------------------------------------------------------------
// Combine: y2 = Y2r - XS; x2 = W_g @ [XS;Y1;y2] + b_g; out = (filt + xin1)*sig(gate)
// ---------------------------------------------------------------------------
__global__ void combine_kernel(const float* __restrict__ Wg, const float* __restrict__ bg,
                               float* __restrict__ out) {
    __shared__ float xs[64][24];
    __shared__ float y1[64][24];
    __shared__ float y2[64][24];
    int b = blockIdx.y, n = blockIdx.x, tid = threadIdx.x;
    size_t row = (size_t)n * JCOLS;
    int cb = b * 64 * 24;

    for (int p = tid; p < 1536; p += 256) {
        int c = p / 24, t = p - c * 24;
        size_t g = row + cb + c * 24 + t;
        float a = g_XSp[g];
        xs[c][t] = a;
        y1[c][t] = g_Y1p[g];
        y2[c][t] = g_Y2r[g] - a;   // (2*S^2 - I) @ XS
    }
    __syncthreads();

    int o = tid & 63, q = tid >> 6;
    float f[6], gg[6];
    float bf = __ldg(&bg[o]), bgt = __ldg(&bg[o + 64]);
#pragma unroll
    for (int m = 0; m < 6; m++) { f[m] = bf; gg[m] = bgt; }
    for (int c = 0; c < 64; c++) {
        float w0f = __ldg(&Wg[o * 192 + 3 * c + 0]);
        float w1f = __ldg(&Wg[o * 192 + 3 * c + 1]);
        float w2f = __ldg(&Wg[o * 192 + 3 * c + 2]);
        float w0g = __ldg(&Wg[(o + 64) * 192 + 3 * c + 0]);
        float w1g = __ldg(&Wg[(o + 64) * 192 + 3 * c + 1]);
        float w2g = __ldg(&Wg[(o + 64) * 192 + 3 * c + 2]);
#pragma unroll
        for (int m = 0; m < 6; m++) {
            int t = q + 4 * m;
            float a = xs[c][t], b1 = y1[c][t], b2 = y2[c][t];
            f[m] = fmaf(w0f, a, fmaf(w1f, b1, fmaf(w2f, b2, f[m])));
            gg[m] = fmaf(w0g, a, fmaf(w1g, b1, fmaf(w2g, b2, gg[m])));
        }
    }
    size_t obase = (((size_t)b * 64 + o) * NNODE + n) * TT;
#pragma unroll
    for (int m = 0; m < 6; m++) {
        int t = q + 4 * m;
        out[obase + t] = (f[m] + g_xin1[obase + t]) * sigmoidf_(gg[m]);
    }
}

// ---------------------------------------------------------------------------
// Host launcher
// ---------------------------------------------------------------------------
extern "C" void kernel_launch(void* const* d_in, const int* in_sizes, int n_in,
                              void* d_out, int out_size) {
    const float* x        = (const float*)d_in[0];
    const float* supports = (const float*)d_in[1];
    const float* CD       = (const float*)d_in[2];
    const float* CS       = (const float*)d_in[3];
    const float* adj      = (const float*)d_in[4];
    const float* W_de     = (const float*)d_in[5];
    const float* b_de     = (const float*)d_in[6];
    const float* Wd       = (const float*)d_in[7];
    const float* W_pro    = (const float*)d_in[8];
    const float* b_pro    = (const float*)d_in[9];
    const float* W_mii    = (const float*)d_in[10];
    const float* b_mii    = (const float*)d_in[11];
    const float* W_1      = (const float*)d_in[12];
    const float* b_1      = (const float*)d_in[13];
    const float* Wq_t     = (const float*)d_in[14];
    const float* bq_t     = (const float*)d_in[15];
    const float* Wk_t     = (const float*)d_in[16];
    const float* bk_t     = (const float*)d_in[17];
    const float* Wv_t     = (const float*)d_in[18];
    const float* bv_t     = (const float*)d_in[19];
    const float* W_c1     = (const float*)d_in[20];
    const float* b_c1     = (const float*)d_in[21];
    const float* Wq_s     = (const float*)d_in[22];
    const float* bq_s     = (const float*)d_in[23];
    const float* Wk_s     = (const float*)d_in[24];
    const float* bk_s     = (const float*)d_in[25];
    const float* Wv_s     = (const float*)d_in[26];
    const float* bv_s     = (const float*)d_in[27];
    const float* W_g      = (const float*)d_in[28];
    const float* b_g      = (const float*)d_in[29];
    float* out = (float*)d_out;

    float *p_Ubig, *p_Z, *p_XSp, *p_Y1p, *p_Y2r;
    cudaGetSymbolAddress((void**)&p_Ubig, g_Ubig);
    cudaGetSymbolAddress((void**)&p_Z,    g_Z);
    cudaGetSymbolAddress((void**)&p_XSp,  g_XSp);
    cudaGetSymbolAddress((void**)&p_Y1p,  g_Y1p);
    cudaGetSymbolAddress((void**)&p_Y2r,  g_Y2r);

    // small precompute
    precompute_kernel<<<256, 256>>>(CD, Wd, CS, W_mii);
    rowsum_kernel<<<NNODE, 256>>>(adj);

    // stage 1: conv1x1 fan-out from x
    k1_kernel<<<dim3(NT / 64, BB), 256>>>(x, CS, W_de, b_de, W_pro, b_pro,
                                          W_1, b_1, Wq_t, bq_t);

    // rank-16 graph propagation: Z = adj @ Ubig
    sgemm128<<<dim3(EB / 128, 8), 256>>>(adj, p_Ubig, p_Z, EB, 1.f);

    // temporal attention + temporal conv -> x1
    attn1_kernel<<<dim3(NNODE, BB), 256>>>(Wk_t, bk_t, Wv_t, bv_t, W_c1, b_c1);

    // spatial attention (S reconstructed from Z) -> XS packed
    attn2_kernel<<<dim3(NNODE, BB), 256>>>(W_mii, b_mii, Wq_s, bq_s, Wk_s, bk_s, Wv_s, bv_s);

    // cheby via recurrence: Y1 = S@XS ; Y2r = 2*S@Y1 (the -XS is folded into combine)
    sgemm128<<<dim3(JCOLS / 128, 8), 256>>>(supports, p_XSp, p_Y1p, JCOLS, 1.f);
    sgemm128<<<dim3(JCOLS / 128, 8), 256>>>(supports, p_Y1p, p_Y2r, JCOLS, 2.f);

    // W_g epilogue + residual + gate
    combine_kernel<<<dim3(NNODE, BB), 256>>>(W_g, b_g, out);

    (void)in_sizes; (void)n_in; (void)out_size;
}

// round 10
// speedup vs baseline: 2.1656x; 2.1632x over previous
#include <cuda_runtime.h>
#include <math.h>

// ---------------------------------------------------------------------------
// Problem constants
// ---------------------------------------------------------------------------
#define BB   16
#define CIN  32
#define COUT 64
#define NNODE 1024
#define TT   24
#define NT   (NNODE*TT)        // 24576
#define SDIM 16
#define EB   (SDIM*BB*TT)      // 6144  cols of Ubig / Z
#define JCOLS (BB*COUT*TT)     // 24576 cols of XSp / Y1p / Y2r
#define BIG  (BB*COUT*NT)      // 25165824

// packed transposed-weight scratch offsets (floats)
#define WT_DQ1 0        // [(i*64+o)*4] = {W_de, Wq_t, W_1, 0}        8192
#define WT_KVT 8192     // [(i*64+c)*2] = {Wk_t, Wv_t}                8192
#define WT_C1  16384    // [(i*64+o)*4] = {w0, w1, w2, 0}             16384
#define WT_QS  32768    // [i*64+c]     = Wq_s                        4096
#define WT_KVS 36864    // [(i*64+c)*2] = {Wk_s, Wv_s}                8192
#define WT_G   45056    // [(j*64+o)*2] = {Wg_filt, Wg_gate}          24576

// ---------------------------------------------------------------------------
// Scratch (static device globals -- no allocation allowed)
// ---------------------------------------------------------------------------
__device__ __align__(16) float g_delay[NT];
__device__ __align__(16) float g_M[NNODE*COUT];
__device__ __align__(16) float g_rowsum[NNODE];
__device__ __align__(16) float g_u[BB*NT];
__device__ __align__(16) float g_Ubig[NNODE*EB];
__device__ __align__(16) float g_Z[NNODE*EB];
__device__ __align__(16) float g_xin1[BIG];
__device__ __align__(16) float g_XSp[(size_t)NNODE*JCOLS];
__device__ __align__(16) float g_Y1p[(size_t)NNODE*JCOLS];
__device__ __align__(16) float g_Y2r[(size_t)NNODE*JCOLS];
__device__ __align__(16) float g_WT[69632];

__device__ __forceinline__ float sigmoidf_(float z) {
    return 1.f / (1.f + __expf(-z));
}

// ---------------------------------------------------------------------------
// Weight repack: transpose + pack so warp-lane weight loads are coalesced
// ---------------------------------------------------------------------------
__global__ void repack_weights(const float* __restrict__ W_de, const float* __restrict__ Wq_t,
                               const float* __restrict__ W_1,  const float* __restrict__ Wk_t,
                               const float* __restrict__ Wv_t, const float* __restrict__ W_c1,
                               const float* __restrict__ Wq_s, const float* __restrict__ Wk_s,
                               const float* __restrict__ Wv_s, const float* __restrict__ W_g) {
    int idx = blockIdx.x * 256 + threadIdx.x;   // 0 .. 12287
    if (idx < 2048) {                            // i<32, o<64
        int i = idx >> 6, o = idx & 63;
        g_WT[WT_DQ1 + idx * 4 + 0] = W_de[o * 32 + i];
        g_WT[WT_DQ1 + idx * 4 + 1] = Wq_t[o * 32 + i];
        g_WT[WT_DQ1 + idx * 4 + 2] = W_1[o * 32 + i];
        g_WT[WT_DQ1 + idx * 4 + 3] = 0.f;
    }
    if (idx < 4096) {                            // i<64, c<64
        int i = idx >> 6, c = idx & 63;
        g_WT[WT_KVT + idx * 2 + 0] = Wk_t[c * 64 + i];
        g_WT[WT_KVT + idx * 2 + 1] = Wv_t[c * 64 + i];
        g_WT[WT_KVS + idx * 2 + 0] = Wk_s[c * 64 + i];
        g_WT[WT_KVS + idx * 2 + 1] = Wv_s[c * 64 + i];
        g_WT[WT_QS + idx] = Wq_s[c * 64 + i];
        g_WT[WT_C1 + idx * 4 + 0] = W_c1[(c * 64 + i) * 3 + 0];
        g_WT[WT_C1 + idx * 4 + 1] = W_c1[(c * 64 + i) * 3 + 1];
        g_WT[WT_C1 + idx * 4 + 2] = W_c1[(c * 64 + i) * 3 + 2];
        g_WT[WT_C1 + idx * 4 + 3] = 0.f;
    }
    if (idx < 12288) {                           // j<192, o<64
        int j = idx >> 6, o = idx & 63;
        g_WT[WT_G + idx * 2 + 0] = W_g[o * 192 + j];
        g_WT[WT_G + idx * 2 + 1] = W_g[(o + 64) * 192 + j];
    }
}

// ---------------------------------------------------------------------------
// Precompute: delay(n,t), M = CS @ W_mii^T
// ---------------------------------------------------------------------------
__global__ void precompute_kernel(const float* __restrict__ CD,
                                  const float* __restrict__ Wd,
                                  const float* __restrict__ CS,
                                  const float* __restrict__ W_mii) {
    int idx = blockIdx.x * 256 + threadIdx.x;
    if (idx < NT) {
        int n = idx / TT, t = idx - n * TT;
        float a = 0.f;
#pragma unroll
        for (int d = 0; d < 16; d++) a = fmaf(CD[n * 16 + d], Wd[d * TT + t], a);
        g_delay[idx] = sigmoidf_(tanhf(a));
    }
    if (idx < NNODE * COUT) {
        int n = idx / COUT, o = idx - n * COUT;
        float a = 0.f;
#pragma unroll
        for (int e = 0; e < 16; e++) a = fmaf(CS[n * 16 + e], W_mii[o * 16 + e], a);
        g_M[idx] = a;
    }
}

__global__ void rowsum_kernel(const float* __restrict__ adj) {
    __shared__ float red[256];
    int n = blockIdx.x;
    float s = 0.f;
    for (int m = threadIdx.x; m < NNODE; m += 256) s += adj[(size_t)n * NNODE + m];
    red[threadIdx.x] = s;
    __syncthreads();
    for (int w = 128; w > 0; w >>= 1) {
        if (threadIdx.x < w) red[threadIdx.x] += red[threadIdx.x + w];
        __syncthreads();
    }
    if (threadIdx.x == 0) g_rowsum[n] = red[0];
}

// ---------------------------------------------------------------------------
// u + Ubig (rank-16 factorization of the S graph propagation)
// ---------------------------------------------------------------------------
__global__ void u_kernel(const float* __restrict__ x, const float* __restrict__ W_pro,
                         const float* __restrict__ b_pro, const float* __restrict__ CS) {
    int b = blockIdx.y;
    int j = blockIdx.x * 256 + threadIdx.x;
    float u = __ldg(&b_pro[0]);
#pragma unroll 8
    for (int i = 0; i < 32; i++)
        u = fmaf(__ldg(&W_pro[i]), x[((size_t)(b * 32 + i)) * NT + j], u);
    g_u[(size_t)b * NT + j] = u;
    int n = j / TT, t = j - n * TT;
#pragma unroll
    for (int e = 0; e < 16; e++)
        g_Ubig[(size_t)n * EB + e * (BB * TT) + b * TT + t] = __ldg(&CS[n * 16 + e]) * u;
}

// ---------------------------------------------------------------------------
// Generic fp32 GEMM: C = alpha * A(1024 x 1024) @ B(1024 x Nc), row-major.
// ---------------------------------------------------------------------------
__global__ void sgemm128(const float* __restrict__ A, const float* __restrict__ B,
                         float* __restrict__ C, int Nc, float alpha) {
    const int Kd = 1024;
    __shared__ float As[8][128];
    __shared__ float Bs[8][128];
    int tid = threadIdx.x;
    int bm = blockIdx.y * 128;
    int bn = blockIdx.x * 128;
    int tx = tid & 15, ty = tid >> 4;

    float acc[8][8];
#pragma unroll
    for (int i = 0; i < 8; i++)
#pragma unroll
        for (int j = 0; j < 8; j++) acc[i][j] = 0.f;

    int a_row = tid >> 1;
    int a_col = (tid & 1) << 2;
    int b_row = tid >> 5;
    int b_col = (tid & 31) << 2;
    const float* Aptr = A + (size_t)(bm + a_row) * Kd + a_col;
    const float* Bptr = B + (size_t)b_row * Nc + bn + b_col;

    for (int k0 = 0; k0 < Kd; k0 += 8) {
        float4 av = *(const float4*)(Aptr + k0);
        As[a_col + 0][a_row] = av.x;
        As[a_col + 1][a_row] = av.y;
        As[a_col + 2][a_row] = av.z;
        As[a_col + 3][a_row] = av.w;
        float4 bv = *(const float4*)(Bptr + (size_t)k0 * Nc);
        *(float4*)&Bs[b_row][b_col] = bv;
        __syncthreads();
#pragma unroll
        for (int kk = 0; kk < 8; kk++) {
            float a[8], bb[8];
            *(float4*)&a[0] = *(const float4*)&As[kk][ty * 4];
            *(float4*)&a[4] = *(const float4*)&As[kk][64 + ty * 4];
            *(float4*)&bb[0] = *(const float4*)&Bs[kk][tx * 4];
            *(float4*)&bb[4] = *(const float4*)&Bs[kk][64 + tx * 4];
#pragma unroll
            for (int i = 0; i < 8; i++)
#pragma unroll
                for (int j = 0; j < 8; j++) acc[i][j] = fmaf(a[i], bb[j], acc[i][j]);
        }
        __syncthreads();
    }

#pragma unroll
    for (int ih = 0; ih < 2; ih++)
#pragma unroll
        for (int i = 0; i < 4; i++) {
            int r = bm + ih * 64 + ty * 4 + i;
#pragma unroll
            for (int jh = 0; jh < 2; jh++) {
                float4 v;
                v.x = alpha * acc[ih * 4 + i][jh * 4 + 0];
                v.y = alpha * acc[ih * 4 + i][jh * 4 + 1];
                v.z = alpha * acc[ih * 4 + i][jh * 4 + 2];
                v.w = alpha * acc[ih * 4 + i][jh * 4 + 3];
                *(float4*)&C[(size_t)r * Nc + bn + jh * 64 + tx * 4] = v;
            }
        }
}

// ---------------------------------------------------------------------------
// MEGA kernel: per (b,n) tile does
//   conv1x1(x)->{D*delay, Qt, xin1}; temporal attn; +xin1; conv_t -> x1;
//   Qs(x1); S from rank-16 Z; spatial attn -> XS (packed for cheby GEMMs)
// All intermediates stay in shared memory.
// ---------------------------------------------------------------------------
__global__ void __launch_bounds__(256) mega_kernel(
    const float* __restrict__ x, const float* __restrict__ W_mii,
    const float* __restrict__ b_mii,
    const float* __restrict__ b_de, const float* __restrict__ bq_t,
    const float* __restrict__ b_1,  const float* __restrict__ bk_t,
    const float* __restrict__ bv_t, const float* __restrict__ b_c1,
    const float* __restrict__ bq_s, const float* __restrict__ bk_s,
    const float* __restrict__ bv_s) {
    __shared__ float xs[32][25];
    __shared__ float sD[64][25];
    __shared__ float sQ[64][25];
    __shared__ float sK[64][25];
    __shared__ float sV[64][25];
    __shared__ float sX1[64][25];
    __shared__ float sA[24][25];
    __shared__ float sZ[16][24];
    __shared__ float su[24], sdel[24], sM[64];
    __shared__ float sWm[64][16];

    int b = blockIdx.y, n = blockIdx.x, tid = threadIdx.x;
    int o = tid >> 2, q = tid & 3;

    for (int p = tid; p < 768; p += 256) {
        int i = p / 24, t = p - i * 24;
        xs[i][t] = x[((size_t)(b * 32 + i) * NNODE + n) * TT + t];
    }
    for (int p = tid; p < 384; p += 256) {
        int e = p / 24, t = p - e * 24;
        sZ[e][t] = g_Z[(size_t)n * EB + e * (BB * TT) + b * TT + t];
    }
    for (int p = tid; p < 1024; p += 256) sWm[p >> 4][p & 15] = W_mii[p];
    if (tid < 24) {
        su[tid] = g_u[(size_t)b * NT + n * TT + tid];
        sdel[tid] = g_delay[n * TT + tid];
    }
    if (tid < 64) sM[tid] = g_M[n * 64 + tid];
    __syncthreads();

    // ---- D(*delay), Qt, xin1 ----
    {
        float aD[6], aQ[6], aX[6];
        float bd = __ldg(&b_de[o]), bq = __ldg(&bq_t[o]), bx = __ldg(&b_1[o]);
#pragma unroll
        for (int m = 0; m < 6; m++) { aD[m] = bd; aQ[m] = bq; aX[m] = bx; }
#pragma unroll 4
        for (int i = 0; i < 32; i++) {
            float4 w = *(const float4*)&g_WT[WT_DQ1 + (i * 64 + o) * 4];
#pragma unroll
            for (int m = 0; m < 6; m++) {
                float xv = xs[i][q + 4 * m];
                aD[m] = fmaf(w.x, xv, aD[m]);
                aQ[m] = fmaf(w.y, xv, aQ[m]);
                aX[m] = fmaf(w.z, xv, aX[m]);
            }
        }
        size_t gb = (((size_t)b * 64 + o) * NNODE + n) * TT;
#pragma unroll
        for (int m = 0; m < 6; m++) {
            int t = q + 4 * m;
            sD[o][t] = aD[m] * sdel[t];
            sQ[o][t] = aQ[m];
            sX1[o][t] = aX[m];
            g_xin1[gb + t] = aX[m];
        }
    }
    __syncthreads();

    // ---- K,V = conv1x1(D) ----
    {
        float ak[6], av[6];
        float bkc = __ldg(&bk_t[o]), bvc = __ldg(&bv_t[o]);
#pragma unroll
        for (int m = 0; m < 6; m++) { ak[m] = bkc; av[m] = bvc; }
#pragma unroll 4
        for (int i = 0; i < 64; i++) {
            float2 w = *(const float2*)&g_WT[WT_KVT + (i * 64 + o) * 2];
#pragma unroll
            for (int m = 0; m < 6; m++) {
                float d = sD[i][q + 4 * m];
                ak[m] = fmaf(w.x, d, ak[m]);
                av[m] = fmaf(w.y, d, av[m]);
            }
        }
#pragma unroll
        for (int m = 0; m < 6; m++) { sK[o][q + 4 * m] = ak[m]; sV[o][q + 4 * m] = av[m]; }
    }
    __syncthreads();

    // ---- scores + softmax ----
    for (int p = tid; p < 576; p += 256) {
        int t = p / 24, s = p - t * 24;
        float acc = 0.f;
#pragma unroll
        for (int c = 0; c < 64; c++) acc = fmaf(sQ[c][t], sK[c][s], acc);
        sA[t][s] = acc * 0.125f;
    }
    __syncthreads();
    if (tid < 24) {
        float mx = -1e30f;
        for (int s = 0; s < 24; s++) mx = fmaxf(mx, sA[tid][s]);
        float sum = 0.f;
        for (int s = 0; s < 24; s++) { float e = __expf(sA[tid][s] - mx); sA[tid][s] = e; sum += e; }
        float inv = 1.f / sum;
        for (int s = 0; s < 24; s++) sA[tid][s] *= inv;
    }
    __syncthreads();

    // ---- XD = A@V + xin1 (into sX1) ----
    for (int p = tid; p < 1536; p += 256) {
        int c = p / 24, t = p - c * 24;
        float acc = 0.f;
#pragma unroll
        for (int s = 0; s < 24; s++) acc = fmaf(sA[t][s], sV[c][s], acc);
        sX1[c][t] += acc;
    }
    __syncthreads();

    // ---- temporal conv (k=3, pad 1): x1 -> sD ----
    {
        float acc[6];
        float bo = __ldg(&b_c1[o]);
#pragma unroll
        for (int m = 0; m < 6; m++) acc[m] = bo;
#pragma unroll 4
        for (int i = 0; i < 64; i++) {
            float4 w = *(const float4*)&g_WT[WT_C1 + (i * 64 + o) * 4];
#pragma unroll
            for (int m = 0; m < 6; m++) {
                int t = q + 4 * m;
                float xm = (t > 0) ? sX1[i][t - 1] : 0.f;
                float x0 = sX1[i][t];
                float xp = (t < 23) ? sX1[i][t + 1] : 0.f;
                acc[m] = fmaf(w.x, xm, fmaf(w.y, x0, fmaf(w.z, xp, acc[m])));
            }
        }
#pragma unroll
        for (int m = 0; m < 6; m++) sD[o][q + 4 * m] = acc[m];
    }
    __syncthreads();

    // ---- Qs = conv1x1(x1) -> sQ ;  S (rank-16 recon) -> sV ----
    {
        float a[6];
        float bqc = __ldg(&bq_s[o]);
#pragma unroll
        for (int m = 0; m < 6; m++) a[m] = bqc;
#pragma unroll 4
        for (int i = 0; i < 64; i++) {
            float w = __ldg(&g_WT[WT_QS + i * 64 + o]);
#pragma unroll
            for (int m = 0; m < 6; m++) a[m] = fmaf(w, sD[i][q + 4 * m], a[m]);
        }
#pragma unroll
        for (int m = 0; m < 6; m++) sQ[o][q + 4 * m] = a[m];
    }
    {
        float rs1 = 1.f + g_rowsum[n];
        for (int p = tid; p < 1536; p += 256) {
            int c = p / 24, t = p - c * 24;
            float a = __ldg(&b_mii[c]) * rs1 + su[t] * sM[c];
#pragma unroll
            for (int e = 0; e < 16; e++) a = fmaf(sWm[c][e], sZ[e][t], a);
            sV[c][t] = a;
        }
    }
    __syncthreads();

    // ---- Ks,Vs = conv1x1(S): S in sV -> K into sK, V into sX1 ----
    {
        float ak[6], av[6];
        float bkc = __ldg(&bk_s[o]), bvc = __ldg(&bv_s[o]);
#pragma unroll
        for (int m = 0; m < 6; m++) { ak[m] = bkc; av[m] = bvc; }
#pragma unroll 4
        for (int i = 0; i < 64; i++) {
            float2 w = *(const float2*)&g_WT[WT_KVS + (i * 64 + o) * 2];
#pragma unroll
            for (int m = 0; m < 6; m++) {
                float d = sV[i][q + 4 * m];
                ak[m] = fmaf(w.x, d, ak[m]);
                av[m] = fmaf(w.y, d, av[m]);
            }
        }
#pragma unroll
        for (int m = 0; m < 6; m++) { sK[o][q + 4 * m] = ak[m]; sX1[o][q + 4 * m] = av[m]; }
    }
    __syncthreads();

    // ---- scores + softmax ----
    for (int p = tid; p < 576; p += 256) {
        int t = p / 24, s = p - t * 24;
        float acc = 0.f;
#pragma unroll
        for (int c = 0; c < 64; c++) acc = fmaf(sQ[c][t], sK[c][s], acc);
        sA[t][s] = acc * 0.125f;
    }
    __syncthreads();
    if (tid < 24) {
        float mx = -1e30f;
        for (int s = 0; s < 24; s++) mx = fmaxf(mx, sA[tid][s]);
        float sum = 0.f;
        for (int s = 0; s < 24; s++) { float e = __expf(sA[tid][s] - mx); sA[tid][s] = e; sum += e; }
        float inv = 1.f / sum;
        for (int s = 0; s < 24; s++) sA[tid][s] *= inv;
    }
    __syncthreads();

    // ---- XS = A@V -> packed (n, b*c*t) for cheby GEMMs ----
    for (int p = tid; p < 1536; p += 256) {
        int c = p / 24, t = p - c * 24;
        float acc = 0.f;
#pragma unroll
        for (int s = 0; s < 24; s++) acc = fmaf(sA[t][s], sX1[c][s], acc);
        g_XSp[(size_t)n * JCOLS + (b * 64 + c) * 24 + t] = acc;
    }
}

// ---------------------------------------------------------------------------
// Combine: y2 = Y2r - XS; x2 = W_g @ [XS;Y1;y2] + b_g; out = (filt+xin1)*sig(gate)
// ---------------------------------------------------------------------------
__global__ void __launch_bounds__(256) combine_kernel(const float* __restrict__ bg,
                                                      float* __restrict__ out) {
    __shared__ float xs[64][25];
    __shared__ float y1[64][25];
    __shared__ float y2[64][25];
    int b = blockIdx.y, n = blockIdx.x, tid = threadIdx.x;
    size_t row = (size_t)n * JCOLS;
    int cb = b * 64 * 24;

    for (int p = tid; p < 1536; p += 256) {
        int c = p / 24, t = p - c * 24;
        size_t g = row + cb + c * 24 + t;
        float a = g_XSp[g];
        xs[c][t] = a;
        y1[c][t] = g_Y1p[g];
        y2[c][t] = g_Y2r[g] - a;   // (2*S^2 - I) @ XS
    }
    __syncthreads();

    int o = tid & 63, q = tid >> 6;
    float f[6], gg[6];
    float bf = __ldg(&bg[o]), bgt = __ldg(&bg[o + 64]);
#pragma unroll
    for (int m = 0; m < 6; m++) { f[m] = bf; gg[m] = bgt; }
#pragma unroll 2
    for (int c = 0; c < 64; c++) {
        float2 w0 = *(const float2*)&g_WT[WT_G + ((3 * c + 0) * 64 + o) * 2];
        float2 w1 = *(const float2*)&g_WT[WT_G + ((3 * c + 1) * 64 + o) * 2];
        float2 w2 = *(const float2*)&g_WT[WT_G + ((3 * c + 2) * 64 + o) * 2];
#pragma unroll
        for (int m = 0; m < 6; m++) {
            int t = q + 4 * m;
            float a = xs[c][t], b1 = y1[c][t], b2 = y2[c][t];
            f[m]  = fmaf(w0.x, a, fmaf(w1.x, b1, fmaf(w2.x, b2, f[m])));
            gg[m] = fmaf(w0.y, a, fmaf(w1.y, b1, fmaf(w2.y, b2, gg[m])));
        }
    }
    size_t obase = (((size_t)b * 64 + o) * NNODE + n) * TT;
#pragma unroll
    for (int m = 0; m < 6; m++) {
        int t = q + 4 * m;
        out[obase + t] = (f[m] + g_xin1[obase + t]) * sigmoidf_(gg[m]);
    }
}

// ---------------------------------------------------------------------------
// Host launcher
// ---------------------------------------------------------------------------
extern "C" void kernel_launch(void* const* d_in, const int* in_sizes, int n_in,
                              void* d_out, int out_size) {
    const float* x        = (const float*)d_in[0];
    const float* supports = (const float*)d_in[1];
    const float* CD       = (const float*)d_in[2];
    const float* CS       = (const float*)d_in[3];
    const float* adj      = (const float*)d_in[4];
    const float* W_de     = (const float*)d_in[5];
    const float* b_de     = (const float*)d_in[6];
    const float* Wd       = (const float*)d_in[7];
    const float* W_pro    = (const float*)d_in[8];
    const float* b_pro    = (const float*)d_in[9];
    const float* W_mii    = (const float*)d_in[10];
    const float* b_mii    = (const float*)d_in[11];
    const float* W_1      = (const float*)d_in[12];
    const float* b_1      = (const float*)d_in[13];
    const float* Wq_t     = (const float*)d_in[14];
    const float* bq_t     = (const float*)d_in[15];
    const float* Wk_t     = (const float*)d_in[16];
    const float* bk_t     = (const float*)d_in[17];
    const float* Wv_t     = (const float*)d_in[18];
    const float* bv_t     = (const float*)d_in[19];
    const float* W_c1     = (const float*)d_in[20];
    const float* b_c1     = (const float*)d_in[21];
    const float* Wq_s     = (const float*)d_in[22];
    const float* bq_s     = (const float*)d_in[23];
    const float* Wk_s     = (const float*)d_in[24];
    const float* bk_s     = (const float*)d_in[25];
    const float* Wv_s     = (const float*)d_in[26];
    const float* bv_s     = (const float*)d_in[27];
    const float* W_g      = (const float*)d_in[28];
    const float* b_g      = (const float*)d_in[29];
    float* out = (float*)d_out;

    float *p_Ubig, *p_Z, *p_XSp, *p_Y1p, *p_Y2r;
    cudaGetSymbolAddress((void**)&p_Ubig, g_Ubig);
    cudaGetSymbolAddress((void**)&p_Z,    g_Z);
    cudaGetSymbolAddress((void**)&p_XSp,  g_XSp);
    cudaGetSymbolAddress((void**)&p_Y1p,  g_Y1p);
    cudaGetSymbolAddress((void**)&p_Y2r,  g_Y2r);

    // weight repack + small precompute
    repack_weights<<<48, 256>>>(W_de, Wq_t, W_1, Wk_t, Wv_t, W_c1,
                                Wq_s, Wk_s, Wv_s, W_g);
    precompute_kernel<<<256, 256>>>(CD, Wd, CS, W_mii);
    rowsum_kernel<<<NNODE, 256>>>(adj);

    // u / Ubig then rank-16 graph propagation: Z = adj @ Ubig
    u_kernel<<<dim3(NT / 256, BB), 256>>>(x, W_pro, b_pro, CS);
    sgemm128<<<dim3(EB / 128, 8), 256>>>(adj, p_Ubig, p_Z, EB, 1.f);

    // fused: conv1x1 fan-out + temporal attn + conv_t + spatial attn -> XS packed
    mega_kernel<<<dim3(NNODE, BB), 256>>>(x, W_mii, b_mii, b_de, bq_t, b_1,
                                          bk_t, bv_t, b_c1, bq_s, bk_s, bv_s);

    // cheby via recurrence: Y1 = S@XS ; Y2r = 2*S@Y1 (the -XS folds into combine)
    sgemm128<<<dim3(JCOLS / 128, 8), 256>>>(supports, p_XSp, p_Y1p, JCOLS, 1.f);
    sgemm128<<<dim3(JCOLS / 128, 8), 256>>>(supports, p_Y1p, p_Y2r, JCOLS, 2.f);

    // W_g epilogue + residual + gate
    combine_kernel<<<dim3(NNODE, BB), 256>>>(b_g, out);

    (void)in_sizes; (void)n_in; (void)out_size;
}